// round 3
// baseline (speedup 1.0000x reference)
#include <cuda_runtime.h>
#include <math.h>
#include <stdint.h>

// ---------------- problem constants ----------------
#define SEQ     2048
#define DM      768
#define DIP     3224      // 2*1536 + 2*64 + 24
#define DINNER  1536
#define CONVCH  1664      // 1536 + 2*64
#define NHEADS  24
#define HD      64
#define DSTATE  64
#define DCONV   4
#define FFN     2048
#define EPS1    1.1920929e-07f
#define EPSG    1e-5f

// ---------------- scratch (single __device__ arena; no allocs) ----------------
constexpr size_t SZ_XN  = (size_t)SEQ * DM;       // 1,572,864
constexpr size_t SZ_ZX  = (size_t)SEQ * DIP;      // 6,602,752
constexpr size_t SZ_XBC = (size_t)SEQ * CONVCH;   // 3,407,872
constexpr size_t SZ_DT  = (size_t)SEQ * NHEADS;   // 49,152
constexpr size_t SZ_Y   = (size_t)SEQ * DINNER;   // 3,145,728
constexpr size_t SZ_G   = (size_t)SEQ * FFN;      // 4,194,304

constexpr size_t OFF_XN  = 0;
constexpr size_t OFF_ZX  = OFF_XN  + SZ_XN;
constexpr size_t OFF_XBC = OFF_ZX  + SZ_ZX;
constexpr size_t OFF_DT  = OFF_XBC + SZ_XBC;
constexpr size_t OFF_Y   = OFF_DT  + SZ_DT;
constexpr size_t OFF_X1  = OFF_Y   + SZ_Y;
constexpr size_t OFF_H   = OFF_X1  + SZ_XN;
constexpr size_t OFF_G   = OFF_H   + SZ_XN;
constexpr size_t OFF_U   = OFF_G   + SZ_G;
constexpr size_t TOTAL_F = OFF_U   + SZ_G;        // ~26.3M floats (~105 MB)

__device__ float g_buf[TOTAL_F];

// Resolve pointer: external (harness) pointer if non-null, else scratch arena + offset.
__device__ __forceinline__ const float* RP(const float* p, size_t off) {
    return p ? p : (const float*)g_buf + off;
}
__device__ __forceinline__ float* WP(float* p, size_t off) {
    return p ? p : g_buf + off;
}

__device__ __forceinline__ float siluf(float v) { return v / (1.0f + expf(-v)); }

// ---------------- block reduce ----------------
__device__ __forceinline__ float blockReduceSum(float v) {
    __shared__ float sh[32];
    int lane = threadIdx.x & 31, wid = threadIdx.x >> 5;
    #pragma unroll
    for (int o = 16; o; o >>= 1) v += __shfl_xor_sync(0xffffffffu, v, o);
    if (lane == 0) sh[wid] = v;
    __syncthreads();
    if (wid == 0) {
        v = (lane < (int)(blockDim.x >> 5)) ? sh[lane] : 0.0f;
        #pragma unroll
        for (int o = 16; o; o >>= 1) v += __shfl_xor_sync(0xffffffffu, v, o);
        if (lane == 0) sh[0] = v;
    }
    __syncthreads();
    return sh[0];
}

// ---------------- RMSNorm: out = x * rsqrt(mean(x^2)+eps) * w ----------------
__global__ __launch_bounds__(256) void rmsnorm_kernel(
    const float* __restrict__ xe, size_t xoff,
    const float* __restrict__ w,
    float* __restrict__ oe, size_t ooff,
    int C, float eps)
{
    const float* x = RP(xe, xoff) + (size_t)blockIdx.x * C;
    float* o = WP(oe, ooff) + (size_t)blockIdx.x * C;
    float ss = 0.0f;
    for (int i = threadIdx.x; i < C; i += 256) { float v = x[i]; ss += v * v; }
    float tot = blockReduceSum(ss);
    float scale = rsqrtf(tot / (float)C + eps);
    for (int i = threadIdx.x; i < C; i += 256) o[i] = x[i] * scale * w[i];
}

// ---------------- Gated RMSNorm (in place over y): v = y * silu(z); y = rmsnorm(v) ----------------
__global__ __launch_bounds__(256) void gated_norm_kernel(const float* __restrict__ w)
{
    __shared__ float sv[DINNER];
    size_t r = blockIdx.x;
    float* y = g_buf + OFF_Y + r * DINNER;
    const float* z = g_buf + OFF_ZX + r * DIP;   // z is first DINNER cols of zxbcdt
    float ss = 0.0f;
    for (int i = threadIdx.x; i < DINNER; i += 256) {
        float v = y[i] * siluf(z[i]);
        sv[i] = v;
        ss += v * v;
    }
    float tot = blockReduceSum(ss);
    float scale = rsqrtf(tot / (float)DINNER + EPSG);
    for (int i = threadIdx.x; i < DINNER; i += 256) y[i] = sv[i] * scale * w[i];
}

// ---------------- causal depthwise conv4 + bias + SiLU ----------------
__global__ __launch_bounds__(256) void conv_silu_kernel(
    const float* __restrict__ cw, const float* __restrict__ cb)
{
    int gid = blockIdx.x * 256 + threadIdx.x;
    if (gid >= SEQ * CONVCH) return;
    int c = gid % CONVCH;
    int t = gid / CONVCH;
    const float* zx = g_buf + OFF_ZX;
    float v = cb[c];
    #pragma unroll
    for (int k = 0; k < DCONV; k++) {
        int tt = t + k - (DCONV - 1);
        if (tt >= 0) v += zx[(size_t)tt * DIP + DINNER + c] * cw[c * DCONV + k];
    }
    g_buf[OFF_XBC + (size_t)t * CONVCH + c] = siluf(v);
}

// ---------------- dt = softplus(dt_raw + dt_bias) ----------------
__global__ __launch_bounds__(256) void dt_kernel(const float* __restrict__ dt_bias)
{
    int gid = blockIdx.x * 256 + threadIdx.x;
    if (gid >= SEQ * NHEADS) return;
    int h = gid % NHEADS;
    int t = gid / NHEADS;
    float v = g_buf[OFF_ZX + (size_t)t * DIP + DINNER + CONVCH + h] + dt_bias[h];
    g_buf[OFF_DT + (size_t)t * NHEADS + h] = (v > 20.0f) ? v : log1pf(expf(v));
}

// ---------------- SSM scan: one block per head; state (64x64) in registers ----------------
// 256 threads: thread owns p = tid>>2 (headdim row), n-chunk (tid&3)*16 (16 state cols).
__global__ __launch_bounds__(256) void scan_kernel(
    const float* __restrict__ A_log, const float* __restrict__ Dv)
{
    const int h = blockIdx.x;
    const int tid = threadIdx.x;
    const int p  = tid >> 2;
    const int nb = (tid & 3) * 16;
    const float A  = -expf(A_log[h]);
    const float Dh = Dv[h];

    __shared__ float sB[DSTATE], sC[DSTATE], sX[HD];
    __shared__ float sdt, sdA;

    float s[16];
    #pragma unroll
    for (int j = 0; j < 16; j++) s[j] = 0.0f;

    const float* xbc = g_buf + OFF_XBC;
    const float* dtb = g_buf + OFF_DT;
    float* yb = g_buf + OFF_Y;

    // software prefetch of t=0 payload per role
    float pre = 0.0f;
    {
        size_t base = 0; // t = 0
        if (tid < 64)        pre = xbc[base + DINNER + tid];            // B
        else if (tid < 128)  pre = xbc[base + DINNER + DSTATE + (tid - 64)]; // C
        else if (tid < 192)  pre = xbc[base + h * HD + (tid - 128)];    // x_h
        else if (tid == 192) pre = dtb[h];                              // dt
    }

    for (int t = 0; t < SEQ; t++) {
        // publish prefetched step-t payload
        if (tid < 64)        sB[tid] = pre;
        else if (tid < 128)  sC[tid - 64] = pre;
        else if (tid < 192)  sX[tid - 128] = pre;
        else if (tid == 192) { sdt = pre; sdA = expf(pre * A); }
        __syncthreads();

        // prefetch t+1 while computing t
        if (t + 1 < SEQ) {
            size_t base = (size_t)(t + 1) * CONVCH;
            if (tid < 64)        pre = xbc[base + DINNER + tid];
            else if (tid < 128)  pre = xbc[base + DINNER + DSTATE + (tid - 64)];
            else if (tid < 192)  pre = xbc[base + h * HD + (tid - 128)];
            else if (tid == 192) pre = dtb[(size_t)(t + 1) * NHEADS + h];
        }

        float dA = sdA;
        float xh = sX[p];
        float dtx = sdt * xh;
        float acc = 0.0f;
        #pragma unroll
        for (int j = 0; j < 16; j++) {
            float b = sB[nb + j];
            float c = sC[nb + j];
            s[j] = s[j] * dA + dtx * b;
            acc += s[j] * c;
        }
        acc += __shfl_xor_sync(0xffffffffu, acc, 1);
        acc += __shfl_xor_sync(0xffffffffu, acc, 2);
        if ((tid & 3) == 0)
            yb[(size_t)t * DINNER + h * HD + p] = acc + Dh * xh;
        __syncthreads();
    }
}

// ---------------- SwiGLU elementwise: g = silu(g) * u ----------------
__global__ __launch_bounds__(256) void swiglu_kernel()
{
    int gid = blockIdx.x * 256 + threadIdx.x;
    if (gid >= SEQ * FFN) return;
    float g = g_buf[OFF_G + gid];
    float u = g_buf[OFF_U + gid];
    g_buf[OFF_G + gid] = siluf(g) * u;
}

// ---------------- Tiled fp32 GEMM: out[M,N] = A[M,K] @ W[N,K]^T (+ res) ----------------
template<int BM, int BN, int TM, int TN>
__global__ __launch_bounds__(256) void gemm_tn(
    const float* __restrict__ Ae, size_t aoff,
    const float* __restrict__ Wm,
    const float* __restrict__ Re, size_t roff, int has_res,
    float* __restrict__ Oe, size_t ooff,
    int M, int N, int K)
{
    constexpr int BK = 16;
    constexpr int LA = (BM * BK) / (4 * 256);  // float4 loads of A per thread
    constexpr int LB = (BN * BK) / (4 * 256);
    static_assert(LA >= 1 && LB >= 1, "tile too small");

    __shared__ float As[BK][BM + 4];
    __shared__ float Ws[BK][BN + 4];

    const float* A = RP(Ae, aoff);
    float* O = WP(Oe, ooff);

    const int tid = threadIdx.x;
    const int bm = blockIdx.y * BM;
    const int bn = blockIdx.x * BN;
    const int tx = tid % (BN / TN);
    const int ty = tid / (BN / TN);

    float acc[TM][TN];
    #pragma unroll
    for (int i = 0; i < TM; i++)
        #pragma unroll
        for (int j = 0; j < TN; j++) acc[i][j] = 0.0f;

    for (int k0 = 0; k0 < K; k0 += BK) {
        #pragma unroll
        for (int l = 0; l < LA; l++) {
            int f = tid + l * 256;
            int row = f >> 2;
            int c4 = (f & 3) * 4;
            float4 v = *reinterpret_cast<const float4*>(&A[(size_t)(bm + row) * K + k0 + c4]);
            As[c4 + 0][row] = v.x; As[c4 + 1][row] = v.y;
            As[c4 + 2][row] = v.z; As[c4 + 3][row] = v.w;
        }
        #pragma unroll
        for (int l = 0; l < LB; l++) {
            int f = tid + l * 256;
            int row = f >> 2;
            int c4 = (f & 3) * 4;
            float4 v = make_float4(0.f, 0.f, 0.f, 0.f);
            if (bn + row < N)
                v = *reinterpret_cast<const float4*>(&Wm[(size_t)(bn + row) * K + k0 + c4]);
            Ws[c4 + 0][row] = v.x; Ws[c4 + 1][row] = v.y;
            Ws[c4 + 2][row] = v.z; Ws[c4 + 3][row] = v.w;
        }
        __syncthreads();

        #pragma unroll
        for (int kk = 0; kk < BK; kk++) {
            float ra[TM], rw[TN];
            #pragma unroll
            for (int i = 0; i < TM; i++) ra[i] = As[kk][ty * TM + i];
            #pragma unroll
            for (int j = 0; j < TN; j++) rw[j] = Ws[kk][tx * TN + j];
            #pragma unroll
            for (int i = 0; i < TM; i++)
                #pragma unroll
                for (int j = 0; j < TN; j++) acc[i][j] += ra[i] * rw[j];
        }
        __syncthreads();
    }

    const float* R = has_res ? RP(Re, roff) : nullptr;
    #pragma unroll
    for (int i = 0; i < TM; i++) {
        int row = bm + ty * TM + i;
        #pragma unroll
        for (int j = 0; j < TN; j++) {
            int col = bn + tx * TN + j;
            if (col < N) {
                float v = acc[i][j];
                if (has_res) v += R[(size_t)row * N + col];
                O[(size_t)row * N + col] = v;
            }
        }
    }
}

// ---------------- launch ----------------
extern "C" void kernel_launch(void* const* d_in, const int* in_sizes, int n_in,
                              void* d_out, int out_size)
{
    const float* x          = (const float*)d_in[0];
    const float* norm1_w    = (const float*)d_in[1];
    const float* norm2_w    = (const float*)d_in[2];
    const float* in_proj_w  = (const float*)d_in[3];
    const float* conv_w     = (const float*)d_in[4];
    const float* conv_b     = (const float*)d_in[5];
    const float* dt_bias    = (const float*)d_in[6];
    const float* A_log      = (const float*)d_in[7];
    const float* Dv         = (const float*)d_in[8];
    const float* ssm_norm_w = (const float*)d_in[9];
    const float* out_proj_w = (const float*)d_in[10];
    const float* gate_w     = (const float*)d_in[11];
    const float* up_w       = (const float*)d_in[12];
    const float* down_w     = (const float*)d_in[13];
    float* out = (float*)d_out;

    // 1) xn = rmsnorm(x, norm1_w)
    rmsnorm_kernel<<<SEQ, 256>>>(x, 0, norm1_w, nullptr, OFF_XN, DM, EPS1);

    // 2) zxbcdt = xn @ in_proj_w^T    [2048 x 3224]
    gemm_tn<128, 128, 8, 8><<<dim3((DIP + 127) / 128, SEQ / 128), 256>>>(
        nullptr, OFF_XN, in_proj_w, nullptr, 0, 0, nullptr, OFF_ZX, SEQ, DIP, DM);

    // 3) conv + silu -> xBC
    conv_silu_kernel<<<(SEQ * CONVCH + 255) / 256, 256>>>(conv_w, conv_b);

    // 4) dt = softplus(dt_raw + bias)
    dt_kernel<<<(SEQ * NHEADS + 255) / 256, 256>>>(dt_bias);

    // 5) sequential SSM scan -> y (includes D skip term)
    scan_kernel<<<NHEADS, 256>>>(A_log, Dv);

    // 6) y = rmsnorm(y * silu(z))   (in place)
    gated_norm_kernel<<<SEQ, 256>>>(ssm_norm_w);

    // 7) x1 = y @ out_proj_w^T + x
    gemm_tn<64, 64, 4, 4><<<dim3(DM / 64, SEQ / 64), 256>>>(
        nullptr, OFF_Y, out_proj_w, x, 0, 1, nullptr, OFF_X1, SEQ, DM, DINNER);

    // 8) h = rmsnorm(x1, norm2_w)
    rmsnorm_kernel<<<SEQ, 256>>>(nullptr, OFF_X1, norm2_w, nullptr, OFF_H, DM, EPS1);

    // 9) g = h @ gate_w^T ; u = h @ up_w^T
    gemm_tn<128, 128, 8, 8><<<dim3(FFN / 128, SEQ / 128), 256>>>(
        nullptr, OFF_H, gate_w, nullptr, 0, 0, nullptr, OFF_G, SEQ, FFN, DM);
    gemm_tn<128, 128, 8, 8><<<dim3(FFN / 128, SEQ / 128), 256>>>(
        nullptr, OFF_H, up_w, nullptr, 0, 0, nullptr, OFF_U, SEQ, FFN, DM);

    // 10) g = silu(g) * u
    swiglu_kernel<<<(SEQ * FFN + 255) / 256, 256>>>();

    // 11) out = g @ down_w^T + x1
    gemm_tn<64, 64, 4, 4><<<dim3(DM / 64, SEQ / 64), 256>>>(
        nullptr, OFF_G, down_w, nullptr, OFF_X1, 1, out, 0, SEQ, DM, FFN);
}

// round 4
// speedup vs baseline: 1.0356x; 1.0356x over previous
#include <cuda_runtime.h>
#include <math.h>
#include <stdint.h>

// ---------------- problem constants ----------------
#define SEQ     2048
#define DM      768
#define DIP     3224      // 2*1536 + 2*64 + 24
#define DINNER  1536
#define CONVCH  1664      // 1536 + 2*64
#define NHEADS  24
#define HD      64
#define DSTATE  64
#define DCONV   4
#define FFN     2048
#define EPS1    1.1920929e-07f
#define EPSG    1e-5f

// ---------------- scratch arena ----------------
constexpr size_t SZ_XN  = (size_t)SEQ * DM;
constexpr size_t SZ_ZX  = (size_t)SEQ * DIP;
constexpr size_t SZ_XBC = (size_t)SEQ * CONVCH;
constexpr size_t SZ_DT  = (size_t)SEQ * NHEADS;
constexpr size_t SZ_DA  = (size_t)SEQ * NHEADS;
constexpr size_t SZ_Y   = (size_t)SEQ * DINNER;
constexpr size_t SZ_G   = (size_t)SEQ * FFN;

constexpr size_t OFF_XN  = 0;
constexpr size_t OFF_ZX  = OFF_XN  + SZ_XN;
constexpr size_t OFF_XBC = OFF_ZX  + SZ_ZX;
constexpr size_t OFF_DT  = OFF_XBC + SZ_XBC;
constexpr size_t OFF_DA  = OFF_DT  + SZ_DT;
constexpr size_t OFF_Y   = OFF_DA  + SZ_DA;
constexpr size_t OFF_X1  = OFF_Y   + SZ_Y;
constexpr size_t OFF_H   = OFF_X1  + SZ_XN;
constexpr size_t OFF_G   = OFF_H   + SZ_XN;
constexpr size_t OFF_U   = OFF_G   + SZ_G;
constexpr size_t TOTAL_F = OFF_U   + SZ_G;

__device__ float g_buf[TOTAL_F];

__device__ __forceinline__ const float* RP(const float* p, size_t off) {
    return p ? p : (const float*)g_buf + off;
}
__device__ __forceinline__ float* WP(float* p, size_t off) {
    return p ? p : g_buf + off;
}

__device__ __forceinline__ float siluf(float v) { return v / (1.0f + expf(-v)); }

// ---------------- block reduce ----------------
__device__ __forceinline__ float blockReduceSum(float v) {
    __shared__ float sh[32];
    int lane = threadIdx.x & 31, wid = threadIdx.x >> 5;
    #pragma unroll
    for (int o = 16; o; o >>= 1) v += __shfl_xor_sync(0xffffffffu, v, o);
    if (lane == 0) sh[wid] = v;
    __syncthreads();
    if (wid == 0) {
        v = (lane < (int)(blockDim.x >> 5)) ? sh[lane] : 0.0f;
        #pragma unroll
        for (int o = 16; o; o >>= 1) v += __shfl_xor_sync(0xffffffffu, v, o);
        if (lane == 0) sh[0] = v;
    }
    __syncthreads();
    return sh[0];
}

// ---------------- RMSNorm ----------------
__global__ __launch_bounds__(256) void rmsnorm_kernel(
    const float* __restrict__ xe, size_t xoff,
    const float* __restrict__ w,
    float* __restrict__ oe, size_t ooff,
    int C, float eps)
{
    const float* x = RP(xe, xoff) + (size_t)blockIdx.x * C;
    float* o = WP(oe, ooff) + (size_t)blockIdx.x * C;
    float ss = 0.0f;
    for (int i = threadIdx.x; i < C; i += 256) { float v = x[i]; ss += v * v; }
    float tot = blockReduceSum(ss);
    float scale = rsqrtf(tot / (float)C + eps);
    for (int i = threadIdx.x; i < C; i += 256) o[i] = x[i] * scale * w[i];
}

// ---------------- Gated RMSNorm ----------------
__global__ __launch_bounds__(256) void gated_norm_kernel(const float* __restrict__ w)
{
    __shared__ float sv[DINNER];
    size_t r = blockIdx.x;
    float* y = g_buf + OFF_Y + r * DINNER;
    const float* z = g_buf + OFF_ZX + r * DIP;
    float ss = 0.0f;
    for (int i = threadIdx.x; i < DINNER; i += 256) {
        float v = y[i] * siluf(z[i]);
        sv[i] = v;
        ss += v * v;
    }
    float tot = blockReduceSum(ss);
    float scale = rsqrtf(tot / (float)DINNER + EPSG);
    for (int i = threadIdx.x; i < DINNER; i += 256) y[i] = sv[i] * scale * w[i];
}

// ---------------- causal depthwise conv4 + bias + SiLU ----------------
__global__ __launch_bounds__(256) void conv_silu_kernel(
    const float* __restrict__ cw, const float* __restrict__ cb)
{
    int gid = blockIdx.x * 256 + threadIdx.x;
    if (gid >= SEQ * CONVCH) return;
    int c = gid % CONVCH;
    int t = gid / CONVCH;
    const float* zx = g_buf + OFF_ZX;
    float v = cb[c];
    #pragma unroll
    for (int k = 0; k < DCONV; k++) {
        int tt = t + k - (DCONV - 1);
        if (tt >= 0) v += zx[(size_t)tt * DIP + DINNER + c] * cw[c * DCONV + k];
    }
    g_buf[OFF_XBC + (size_t)t * CONVCH + c] = siluf(v);
}

// ---------------- dt in full fp32 (exp(dt*A) is error-amplifying) ----------------
// Computes dt_raw = xn @ Wdt^T exactly, then dt = softplus(dt_raw+bias) and dA = exp(dt*A).
__global__ __launch_bounds__(128) void dtprep_kernel(
    const float* __restrict__ W, const float* __restrict__ dt_bias,
    const float* __restrict__ A_log)
{
    int t = blockIdx.x;
    int lane = threadIdx.x & 31, w = threadIdx.x >> 5;
    const float4* xn = (const float4*)(g_buf + OFF_XN + (size_t)t * DM);
    for (int h = w; h < NHEADS; h += 4) {
        const float4* wr = (const float4*)(W + (size_t)(DINNER + CONVCH + h) * DM);
        float s = 0.f;
        for (int i = lane; i < DM / 4; i += 32) {
            float4 a = xn[i], b = wr[i];
            s += a.x * b.x + a.y * b.y + a.z * b.z + a.w * b.w;
        }
        #pragma unroll
        for (int o = 16; o; o >>= 1) s += __shfl_xor_sync(0xffffffffu, s, o);
        if (lane == 0) {
            float v = s + dt_bias[h];
            float dt = (v > 20.f) ? v : log1pf(expf(v));
            g_buf[OFF_DT + (size_t)t * NHEADS + h] = dt;
            g_buf[OFF_DA + (size_t)t * NHEADS + h] = expf(dt * (-expf(A_log[h])));
        }
    }
}

// ---------------- SSM scan: barrier-free, register-pipelined ----------------
// 96 blocks = 24 heads x 4 p-slices of 16 rows. 256 threads:
//   p_local = tid>>4 (16 rows), nq = tid&15 -> states n0 = nq*4 (4 states/thread).
// All operands prefetched 8 steps deep from L2 into registers. No shared memory.
__global__ __launch_bounds__(256) void scan_kernel(const float* __restrict__ Dv)
{
    const int b   = blockIdx.x;
    const int h   = b >> 2;
    const int ps  = b & 3;
    const int tid = threadIdx.x;
    const int pl  = tid >> 4;
    const int nq  = tid & 15;
    const int p   = ps * 16 + pl;
    const int n0  = nq * 4;
    const float Dh = Dv[h];

    const float* xbc = g_buf + OFF_XBC;
    const float* dtb = g_buf + OFF_DT;
    const float* dab = g_buf + OFF_DA;
    float* yb = g_buf + OFF_Y;

    const float* Bcol = xbc + DINNER + n0;
    const float* Ccol = xbc + DINNER + DSTATE + n0;
    const float* Xcol = xbc + h * HD + p;

    constexpr int PF = 8;
    float4 rB[PF], rC[PF];
    float rx[PF], rdt[PF], rdA[PF];

    #pragma unroll
    for (int i = 0; i < PF; i++) {
        rB[i]  = *(const float4*)(Bcol + (size_t)i * CONVCH);
        rC[i]  = *(const float4*)(Ccol + (size_t)i * CONVCH);
        rx[i]  = Xcol[(size_t)i * CONVCH];
        rdt[i] = dtb[(size_t)i * NHEADS + h];
        rdA[i] = dab[(size_t)i * NHEADS + h];
    }

    float s0 = 0.f, s1 = 0.f, s2 = 0.f, s3 = 0.f;
    const bool writer = (nq == 0);

    for (int t = 0; t < SEQ; t += PF) {
        #pragma unroll
        for (int u = 0; u < PF; u++) {
            float dA = rdA[u], dt = rdt[u], x = rx[u];
            float4 Bv = rB[u], Cv = rC[u];
            int tn = t + u + PF;
            if (tn < SEQ) {
                rB[u]  = *(const float4*)(Bcol + (size_t)tn * CONVCH);
                rC[u]  = *(const float4*)(Ccol + (size_t)tn * CONVCH);
                rx[u]  = Xcol[(size_t)tn * CONVCH];
                rdt[u] = dtb[(size_t)tn * NHEADS + h];
                rdA[u] = dab[(size_t)tn * NHEADS + h];
            }
            float dtx = dt * x;
            s0 = s0 * dA + dtx * Bv.x; float acc = s0 * Cv.x;
            s1 = s1 * dA + dtx * Bv.y; acc += s1 * Cv.y;
            s2 = s2 * dA + dtx * Bv.z; acc += s2 * Cv.z;
            s3 = s3 * dA + dtx * Bv.w; acc += s3 * Cv.w;
            acc += __shfl_xor_sync(0xffffffffu, acc, 1);
            acc += __shfl_xor_sync(0xffffffffu, acc, 2);
            acc += __shfl_xor_sync(0xffffffffu, acc, 4);
            acc += __shfl_xor_sync(0xffffffffu, acc, 8);
            if (writer)
                yb[(size_t)(t + u) * DINNER + h * HD + p] = acc + Dh * x;
        }
    }
}

// ---------------- SwiGLU elementwise ----------------
__global__ __launch_bounds__(256) void swiglu_kernel()
{
    int gid = blockIdx.x * 256 + threadIdx.x;
    if (gid >= SEQ * FFN) return;
    float g = g_buf[OFF_G + gid];
    float u = g_buf[OFF_U + gid];
    g_buf[OFF_G + gid] = siluf(g) * u;
}

// ---------------- 3xTF32 tensor-core GEMM: out[M,N] = A[M,K] @ W[N,K]^T (+res) ----------------
__device__ __forceinline__ void mma8(float (&c)[4], const uint32_t* a, const uint32_t* b) {
    asm volatile(
        "mma.sync.aligned.m16n8k8.row.col.f32.tf32.tf32.f32 "
        "{%0,%1,%2,%3}, {%4,%5,%6,%7}, {%8,%9}, {%0,%1,%2,%3};\n"
        : "+f"(c[0]), "+f"(c[1]), "+f"(c[2]), "+f"(c[3])
        : "r"(a[0]), "r"(a[1]), "r"(a[2]), "r"(a[3]), "r"(b[0]), "r"(b[1]));
}

__device__ __forceinline__ float to_tf32(float x) {
    uint32_t u;
    asm("cvt.rna.tf32.f32 %0, %1;" : "=r"(u) : "f"(x));
    return __uint_as_float(u);
}

__device__ __forceinline__ void split4(float4 v, float4& hi, float4& lo) {
    hi.x = to_tf32(v.x); lo.x = to_tf32(v.x - hi.x);
    hi.y = to_tf32(v.y); lo.y = to_tf32(v.y - hi.y);
    hi.z = to_tf32(v.z); lo.z = to_tf32(v.z - hi.z);
    hi.w = to_tf32(v.w); lo.w = to_tf32(v.w - hi.w);
}

#define GBM 128
#define GBN 128
#define GBK 16
#define GLDT 20     // BK + 4 pad: bank = (4g+c) mod 32 -> conflict-free frag loads
constexpr int GEMM_SMEM_BYTES = 4 * 2 * GBM * GLDT * 4; // Ah,Al,Bh,Bl x 2 stages

__global__ __launch_bounds__(256) void gemm_tf32(
    const float* __restrict__ Ae, size_t aoff,
    const float* __restrict__ Wm,
    const float* __restrict__ Re, size_t roff, int has_res,
    float* __restrict__ Oe, size_t ooff,
    int M, int N, int K)
{
    extern __shared__ float sm[];
    float* Ah = sm;
    float* Al = Ah + 2 * GBM * GLDT;
    float* Bh = Al + 2 * GBM * GLDT;
    float* Bl = Bh + 2 * GBN * GLDT;

    const float* A = RP(Ae, aoff);
    float* O = WP(Oe, ooff);

    const int tid  = threadIdx.x;
    const int lane = tid & 31;
    const int wid  = tid >> 5;
    const int wm   = (wid & 1) * 64;
    const int wn   = (wid >> 1) * 32;
    const int g    = lane >> 2;
    const int cc   = lane & 3;
    const int bm   = blockIdx.y * GBM;
    const int bn   = blockIdx.x * GBN;

    const int r0 = tid >> 2;          // staging row (0..63), +64 for l=1
    const int c4 = (tid & 3) * 4;     // staging col

    float acc[4][4][4];
    #pragma unroll
    for (int i = 0; i < 4; i++)
        #pragma unroll
        for (int j = 0; j < 4; j++)
            #pragma unroll
            for (int q = 0; q < 4; q++) acc[i][j][q] = 0.f;

    float4 ra[2], rb[2];

    const int KT = K / GBK;

    // ---- prologue: load tile 0, stage it ----
    #pragma unroll
    for (int l = 0; l < 2; l++) {
        int row = r0 + l * 64;
        ra[l] = *(const float4*)(A + (size_t)(bm + row) * K + c4);
        int n = bn + row;
        rb[l] = (n < N) ? *(const float4*)(Wm + (size_t)n * K + c4)
                        : make_float4(0.f, 0.f, 0.f, 0.f);
    }
    #pragma unroll
    for (int l = 0; l < 2; l++) {
        int row = r0 + l * 64;
        int base = row * GLDT + c4;
        float4 h4, l4;
        split4(ra[l], h4, l4);
        *(float4*)&Ah[base] = h4; *(float4*)&Al[base] = l4;
        split4(rb[l], h4, l4);
        *(float4*)&Bh[base] = h4; *(float4*)&Bl[base] = l4;
    }
    __syncthreads();

    for (int kt = 0; kt < KT; kt++) {
        const int s = kt & 1;
        const bool nxt = (kt + 1 < KT);
        if (nxt) {
            #pragma unroll
            for (int l = 0; l < 2; l++) {
                int row = r0 + l * 64;
                ra[l] = *(const float4*)(A + (size_t)(bm + row) * K + (kt + 1) * GBK + c4);
                int n = bn + row;
                rb[l] = (n < N) ? *(const float4*)(Wm + (size_t)n * K + (kt + 1) * GBK + c4)
                                : make_float4(0.f, 0.f, 0.f, 0.f);
            }
        }

        // ---- compute on stage s ----
        {
            const uint32_t* AhU = (const uint32_t*)(Ah + s * GBM * GLDT);
            const uint32_t* AlU = (const uint32_t*)(Al + s * GBM * GLDT);
            const uint32_t* BhU = (const uint32_t*)(Bh + s * GBN * GLDT);
            const uint32_t* BlU = (const uint32_t*)(Bl + s * GBN * GLDT);
            #pragma unroll
            for (int ks = 0; ks < 2; ks++) {
                const int k0 = ks * 8 + cc;
                uint32_t ah[4][4], al[4][4];
                #pragma unroll
                for (int i = 0; i < 4; i++) {
                    int m0 = (wm + i * 16 + g) * GLDT + k0;
                    int m1 = m0 + 8 * GLDT;
                    ah[i][0] = AhU[m0];     ah[i][1] = AhU[m1];
                    ah[i][2] = AhU[m0 + 4]; ah[i][3] = AhU[m1 + 4];
                    al[i][0] = AlU[m0];     al[i][1] = AlU[m1];
                    al[i][2] = AlU[m0 + 4]; al[i][3] = AlU[m1 + 4];
                }
                #pragma unroll
                for (int j = 0; j < 4; j++) {
                    int nb0 = (wn + j * 8 + g) * GLDT + k0;
                    uint32_t bh[2] = { BhU[nb0], BhU[nb0 + 4] };
                    uint32_t bl[2] = { BlU[nb0], BlU[nb0 + 4] };
                    #pragma unroll
                    for (int i = 0; i < 4; i++) {
                        mma8(acc[i][j], ah[i], bh);   // hi*hi
                        mma8(acc[i][j], al[i], bh);   // lo*hi
                        mma8(acc[i][j], ah[i], bl);   // hi*lo
                    }
                }
            }
        }

        if (nxt) {
            #pragma unroll
            for (int l = 0; l < 2; l++) {
                int row = r0 + l * 64;
                int base = (1 - s) * GBM * GLDT + row * GLDT + c4;
                float4 h4, l4;
                split4(ra[l], h4, l4);
                *(float4*)&Ah[base] = h4; *(float4*)&Al[base] = l4;
                split4(rb[l], h4, l4);
                *(float4*)&Bh[base] = h4; *(float4*)&Bl[base] = l4;
            }
        }
        __syncthreads();
    }

    // ---- epilogue ----
    const float* R = has_res ? RP(Re, roff) : nullptr;
    #pragma unroll
    for (int i = 0; i < 4; i++) {
        int row = bm + wm + i * 16 + g;
        #pragma unroll
        for (int j = 0; j < 4; j++) {
            int col = bn + wn + j * 8 + 2 * cc;
            if (col < N) {
                size_t o0 = (size_t)row * N + col;
                size_t o1 = (size_t)(row + 8) * N + col;
                float2 v0 = make_float2(acc[i][j][0], acc[i][j][1]);
                float2 v1 = make_float2(acc[i][j][2], acc[i][j][3]);
                if (has_res) {
                    float2 q0 = *(const float2*)(R + o0);
                    float2 q1 = *(const float2*)(R + o1);
                    v0.x += q0.x; v0.y += q0.y;
                    v1.x += q1.x; v1.y += q1.y;
                }
                *(float2*)(O + o0) = v0;
                *(float2*)(O + o1) = v1;
            }
        }
    }
}

// ---------------- launch ----------------
extern "C" void kernel_launch(void* const* d_in, const int* in_sizes, int n_in,
                              void* d_out, int out_size)
{
    const float* x          = (const float*)d_in[0];
    const float* norm1_w    = (const float*)d_in[1];
    const float* norm2_w    = (const float*)d_in[2];
    const float* in_proj_w  = (const float*)d_in[3];
    const float* conv_w     = (const float*)d_in[4];
    const float* conv_b     = (const float*)d_in[5];
    const float* dt_bias    = (const float*)d_in[6];
    const float* A_log      = (const float*)d_in[7];
    const float* Dv         = (const float*)d_in[8];
    const float* ssm_norm_w = (const float*)d_in[9];
    const float* out_proj_w = (const float*)d_in[10];
    const float* gate_w     = (const float*)d_in[11];
    const float* up_w       = (const float*)d_in[12];
    const float* down_w     = (const float*)d_in[13];
    float* out = (float*)d_out;

    cudaFuncSetAttribute(gemm_tf32, cudaFuncAttributeMaxDynamicSharedMemorySize,
                         GEMM_SMEM_BYTES);

    // 1) xn = rmsnorm(x, norm1_w)
    rmsnorm_kernel<<<SEQ, 256>>>(x, 0, norm1_w, nullptr, OFF_XN, DM, EPS1);

    // 2) zxbcdt = xn @ in_proj_w^T   [2048 x 3224]
    gemm_tf32<<<dim3((DIP + GBN - 1) / GBN, SEQ / GBM), 256, GEMM_SMEM_BYTES>>>(
        nullptr, OFF_XN, in_proj_w, nullptr, 0, 0, nullptr, OFF_ZX, SEQ, DIP, DM);

    // 3) conv + silu -> xBC
    conv_silu_kernel<<<(SEQ * CONVCH + 255) / 256, 256>>>(conv_w, conv_b);

    // 4) dt (exact fp32 dot) + dA = exp(dt*A)
    dtprep_kernel<<<SEQ, 128>>>(in_proj_w, dt_bias, A_log);

    // 5) SSM scan -> y
    scan_kernel<<<NHEADS * 4, 256>>>(Dv);

    // 6) y = rmsnorm(y * silu(z))
    gated_norm_kernel<<<SEQ, 256>>>(ssm_norm_w);

    // 7) x1 = y @ out_proj_w^T + x
    gemm_tf32<<<dim3(DM / GBN, SEQ / GBM), 256, GEMM_SMEM_BYTES>>>(
        nullptr, OFF_Y, out_proj_w, x, 0, 1, nullptr, OFF_X1, SEQ, DM, DINNER);

    // 8) h = rmsnorm(x1, norm2_w)
    rmsnorm_kernel<<<SEQ, 256>>>(nullptr, OFF_X1, norm2_w, nullptr, OFF_H, DM, EPS1);

    // 9) g = h @ gate_w^T ; u = h @ up_w^T
    gemm_tf32<<<dim3(FFN / GBN, SEQ / GBM), 256, GEMM_SMEM_BYTES>>>(
        nullptr, OFF_H, gate_w, nullptr, 0, 0, nullptr, OFF_G, SEQ, FFN, DM);
    gemm_tf32<<<dim3(FFN / GBN, SEQ / GBM), 256, GEMM_SMEM_BYTES>>>(
        nullptr, OFF_H, up_w, nullptr, 0, 0, nullptr, OFF_U, SEQ, FFN, DM);

    // 10) g = silu(g) * u
    swiglu_kernel<<<(SEQ * FFN + 255) / 256, 256>>>();

    // 11) out = g @ down_w^T + x1
    gemm_tf32<<<dim3(DM / GBN, SEQ / GBM), 256, GEMM_SMEM_BYTES>>>(
        nullptr, OFF_G, down_w, nullptr, OFF_X1, 1, out, 0, SEQ, DM, FFN);
}

// round 12
// speedup vs baseline: 1.9865x; 1.9183x over previous
#include <cuda_runtime.h>
#include <cuda_bf16.h>
#include <math.h>
#include <stdint.h>

// ---------------- problem constants ----------------
#define SEQ     2048
#define DM      768
#define DIP     3224
#define DINNER  1536
#define CONVCH  1664
#define NHEADS  24
#define HD      64
#define DSTATE  64
#define DCONV   4
#define FFN     2048
#define EPS1    1.1920929e-07f
#define EPSG    1e-5f

// ---------------- fp32 scratch arena ----------------
constexpr size_t SZ_XN  = (size_t)SEQ * DM;
constexpr size_t SZ_ZX  = (size_t)SEQ * DIP;
constexpr size_t SZ_XBC = (size_t)SEQ * CONVCH;
constexpr size_t SZ_DT  = (size_t)SEQ * NHEADS;
constexpr size_t SZ_DA  = (size_t)SEQ * NHEADS;
constexpr size_t SZ_Y   = (size_t)SEQ * DINNER;
constexpr size_t SZ_G   = (size_t)SEQ * FFN;

constexpr size_t OFF_XN  = 0;
constexpr size_t OFF_ZX  = OFF_XN  + SZ_XN;
constexpr size_t OFF_XBC = OFF_ZX  + SZ_ZX;
constexpr size_t OFF_DT  = OFF_XBC + SZ_XBC;
constexpr size_t OFF_DA  = OFF_DT  + SZ_DT;
constexpr size_t OFF_Y   = OFF_DA  + SZ_DA;
constexpr size_t OFF_X1  = OFF_Y   + SZ_Y;
constexpr size_t OFF_H   = OFF_X1  + SZ_XN;
constexpr size_t OFF_G   = OFF_H   + SZ_XN;
constexpr size_t OFF_U   = OFF_G   + SZ_G;
constexpr size_t TOTAL_F = OFF_U   + SZ_G;

__device__ float g_buf[TOTAL_F];

// ---------------- bf16 hi/lo arena ----------------
constexpr size_t N_W_IN   = (size_t)DIP * DM;
constexpr size_t N_W_OUT  = (size_t)DM * DINNER;
constexpr size_t N_W_GATE = (size_t)FFN * DM;
constexpr size_t N_W_UP   = (size_t)FFN * DM;
constexpr size_t N_W_DOWN = (size_t)DM * FFN;
constexpr size_t N_XN = SZ_XN;
constexpr size_t N_Y  = SZ_Y;
constexpr size_t N_H  = SZ_XN;
constexpr size_t N_G  = SZ_G;

constexpr size_t BF_W_IN   = 0;
constexpr size_t BF_W_OUT  = BF_W_IN   + 2 * N_W_IN;
constexpr size_t BF_W_GATE = BF_W_OUT  + 2 * N_W_OUT;
constexpr size_t BF_W_UP   = BF_W_GATE + 2 * N_W_GATE;
constexpr size_t BF_W_DOWN = BF_W_UP   + 2 * N_W_UP;
constexpr size_t BF_XN     = BF_W_DOWN + 2 * N_W_DOWN;
constexpr size_t BF_Y      = BF_XN     + 2 * N_XN;
constexpr size_t BF_H      = BF_Y      + 2 * N_Y;
constexpr size_t BF_G      = BF_H      + 2 * N_H;
constexpr size_t TOTAL_BF  = BF_G      + 2 * N_G;

__device__ __align__(256) __nv_bfloat16 g_bf[TOTAL_BF];

__device__ __forceinline__ const float* RP(const float* p, size_t off) {
    return p ? p : (const float*)g_buf + off;
}
__device__ __forceinline__ float* WP(float* p, size_t off) {
    return p ? p : g_buf + off;
}
__device__ __forceinline__ float siluf(float v) { return v / (1.0f + expf(-v)); }

__device__ __forceinline__ void bf_split(float x, __nv_bfloat16& h, __nv_bfloat16& l) {
    h = __float2bfloat16(x);
    l = __float2bfloat16(x - __bfloat162float(h));
}

// ---------------- PTX helpers (legacy, sm_103-safe) ----------------
__device__ __forceinline__ uint32_t smem_u32(const void* p) {
    uint32_t a;
    asm("{ .reg .u64 t; cvta.to.shared.u64 t, %1; cvt.u32.u64 %0, t; }" : "=r"(a) : "l"(p));
    return a;
}
#define CP_ASYNC16(dst, src, sz) \
    asm volatile("cp.async.cg.shared.global [%0], [%1], 16, %2;" \
        :: "r"(dst), "l"(src), "r"(sz) : "memory")
#define CP_COMMIT() asm volatile("cp.async.commit_group;" ::: "memory")
#define CP_WAIT0()  asm volatile("cp.async.wait_group 0;" ::: "memory")
#define CP_WAIT1()  asm volatile("cp.async.wait_group 1;" ::: "memory")

__device__ __forceinline__ void ldsm4(uint32_t* r, uint32_t addr) {
    asm volatile("ldmatrix.sync.aligned.m8n8.x4.shared.b16 {%0,%1,%2,%3}, [%4];"
        : "=r"(r[0]), "=r"(r[1]), "=r"(r[2]), "=r"(r[3]) : "r"(addr));
}
__device__ __forceinline__ void mma16(float (&c)[4], const uint32_t* a,
                                      uint32_t b0, uint32_t b1) {
    asm volatile(
        "mma.sync.aligned.m16n8k16.row.col.f32.bf16.bf16.f32 "
        "{%0,%1,%2,%3},{%4,%5,%6,%7},{%8,%9},{%0,%1,%2,%3};"
        : "+f"(c[0]), "+f"(c[1]), "+f"(c[2]), "+f"(c[3])
        : "r"(a[0]), "r"(a[1]), "r"(a[2]), "r"(a[3]), "r"(b0), "r"(b1));
}

// ---------------- fp32 -> bf16 hi/lo conversion ----------------
__global__ __launch_bounds__(256) void f2bf_kernel(
    const float* __restrict__ ext, size_t soff, size_t bfoff, size_t n)
{
    const float4* src = (const float4*)(RP(ext, soff));
    __nv_bfloat16* hi = g_bf + bfoff;
    __nv_bfloat16* lo = hi + n;
    size_t n4 = n >> 2;
    for (size_t i = (size_t)blockIdx.x * 256 + threadIdx.x; i < n4;
         i += (size_t)gridDim.x * 256) {
        float4 v = src[i];
        __nv_bfloat16 h0, l0, h1, l1, h2, l2, h3, l3;
        bf_split(v.x, h0, l0); bf_split(v.y, h1, l1);
        bf_split(v.z, h2, l2); bf_split(v.w, h3, l3);
        ((ushort4*)hi)[i] = make_ushort4(__bfloat16_as_ushort(h0), __bfloat16_as_ushort(h1),
                                         __bfloat16_as_ushort(h2), __bfloat16_as_ushort(h3));
        ((ushort4*)lo)[i] = make_ushort4(__bfloat16_as_ushort(l0), __bfloat16_as_ushort(l1),
                                         __bfloat16_as_ushort(l2), __bfloat16_as_ushort(l3));
    }
}

// ---------------- block reduce ----------------
__device__ __forceinline__ float blockReduceSum(float v) {
    __shared__ float sh[32];
    int lane = threadIdx.x & 31, wid = threadIdx.x >> 5;
    #pragma unroll
    for (int o = 16; o; o >>= 1) v += __shfl_xor_sync(0xffffffffu, v, o);
    if (lane == 0) sh[wid] = v;
    __syncthreads();
    if (wid == 0) {
        v = (lane < (int)(blockDim.x >> 5)) ? sh[lane] : 0.0f;
        #pragma unroll
        for (int o = 16; o; o >>= 1) v += __shfl_xor_sync(0xffffffffu, v, o);
        if (lane == 0) sh[0] = v;
    }
    __syncthreads();
    return sh[0];
}

// ---------------- RMSNorm (optional fused bf16 hi/lo output) ----------------
__global__ __launch_bounds__(256) void rmsnorm_kernel(
    const float* __restrict__ xe, size_t xoff,
    const float* __restrict__ w,
    float* __restrict__ oe, size_t ooff,
    size_t bfoff, size_t bfn,
    int C, float eps)
{
    const float* x = RP(xe, xoff) + (size_t)blockIdx.x * C;
    float* o = WP(oe, ooff) + (size_t)blockIdx.x * C;
    float ss = 0.0f;
    for (int i = threadIdx.x; i < C; i += 256) { float v = x[i]; ss += v * v; }
    float tot = blockReduceSum(ss);
    float scale = rsqrtf(tot / (float)C + eps);
    __nv_bfloat16* hi = g_bf + bfoff + (size_t)blockIdx.x * C;
    __nv_bfloat16* lo = hi + bfn;
    for (int i = threadIdx.x; i < C; i += 256) {
        float v = x[i] * scale * w[i];
        o[i] = v;
        if (bfn) { __nv_bfloat16 h, l; bf_split(v, h, l); hi[i] = h; lo[i] = l; }
    }
}

// ---------------- Gated RMSNorm -> bf16 y ----------------
__global__ __launch_bounds__(256) void gated_norm_kernel(const float* __restrict__ w)
{
    __shared__ float sv[DINNER];
    size_t r = blockIdx.x;
    const float* y = g_buf + OFF_Y + r * DINNER;
    const float* z = g_buf + OFF_ZX + r * DIP;
    float ss = 0.0f;
    for (int i = threadIdx.x; i < DINNER; i += 256) {
        float v = y[i] * siluf(z[i]);
        sv[i] = v;
        ss += v * v;
    }
    float tot = blockReduceSum(ss);
    float scale = rsqrtf(tot / (float)DINNER + EPSG);
    __nv_bfloat16* hi = g_bf + BF_Y + r * DINNER;
    __nv_bfloat16* lo = hi + N_Y;
    for (int i = threadIdx.x; i < DINNER; i += 256) {
        float v = sv[i] * scale * w[i];
        __nv_bfloat16 h, l; bf_split(v, h, l);
        hi[i] = h; lo[i] = l;
    }
}

// ---------------- causal depthwise conv4 + bias + SiLU ----------------
__global__ __launch_bounds__(256) void conv_silu_kernel(
    const float* __restrict__ cw, const float* __restrict__ cb)
{
    int gid = blockIdx.x * 256 + threadIdx.x;
    if (gid >= SEQ * CONVCH) return;
    int c = gid % CONVCH;
    int t = gid / CONVCH;
    const float* zx = g_buf + OFF_ZX;
    float v = cb[c];
    #pragma unroll
    for (int k = 0; k < DCONV; k++) {
        int tt = t + k - (DCONV - 1);
        if (tt >= 0) v += zx[(size_t)tt * DIP + DINNER + c] * cw[c * DCONV + k];
    }
    g_buf[OFF_XBC + (size_t)t * CONVCH + c] = siluf(v);
}

// ---------------- dt in exact fp32 ----------------
__global__ __launch_bounds__(128) void dtprep_kernel(
    const float* __restrict__ W, const float* __restrict__ dt_bias,
    const float* __restrict__ A_log)
{
    int t = blockIdx.x;
    int lane = threadIdx.x & 31, w = threadIdx.x >> 5;
    const float4* xn = (const float4*)(g_buf + OFF_XN + (size_t)t * DM);
    for (int h = w; h < NHEADS; h += 4) {
        const float4* wr = (const float4*)(W + (size_t)(DINNER + CONVCH + h) * DM);
        float s = 0.f;
        for (int i = lane; i < DM / 4; i += 32) {
            float4 a = xn[i], b = wr[i];
            s += a.x * b.x + a.y * b.y + a.z * b.z + a.w * b.w;
        }
        #pragma unroll
        for (int o = 16; o; o >>= 1) s += __shfl_xor_sync(0xffffffffu, s, o);
        if (lane == 0) {
            float v = s + dt_bias[h];
            float dt = (v > 20.f) ? v : log1pf(expf(v));
            g_buf[OFF_DT + (size_t)t * NHEADS + h] = dt;
            g_buf[OFF_DA + (size_t)t * NHEADS + h] = expf(dt * (-expf(A_log[h])));
        }
    }
}

// ---------------- SSM scan (register pipelined, barrier-free) ----------------
__global__ __launch_bounds__(256) void scan_kernel(const float* __restrict__ Dv)
{
    const int b   = blockIdx.x;
    const int h   = b >> 2;
    const int ps  = b & 3;
    const int tid = threadIdx.x;
    const int pl  = tid >> 4;
    const int nq  = tid & 15;
    const int p   = ps * 16 + pl;
    const int n0  = nq * 4;
    const float Dh = Dv[h];

    const float* xbc = g_buf + OFF_XBC;
    const float* dtb = g_buf + OFF_DT;
    const float* dab = g_buf + OFF_DA;
    float* yb = g_buf + OFF_Y;

    const float* Bcol = xbc + DINNER + n0;
    const float* Ccol = xbc + DINNER + DSTATE + n0;
    const float* Xcol = xbc + h * HD + p;

    constexpr int PF = 8;
    float4 rB[PF], rC[PF];
    float rx[PF], rdt[PF], rdA[PF];

    #pragma unroll
    for (int i = 0; i < PF; i++) {
        rB[i]  = *(const float4*)(Bcol + (size_t)i * CONVCH);
        rC[i]  = *(const float4*)(Ccol + (size_t)i * CONVCH);
        rx[i]  = Xcol[(size_t)i * CONVCH];
        rdt[i] = dtb[(size_t)i * NHEADS + h];
        rdA[i] = dab[(size_t)i * NHEADS + h];
    }

    float s0 = 0.f, s1 = 0.f, s2 = 0.f, s3 = 0.f;
    const bool writer = (nq == 0);

    for (int t = 0; t < SEQ; t += PF) {
        #pragma unroll
        for (int u = 0; u < PF; u++) {
            float dA = rdA[u], dt = rdt[u], x = rx[u];
            float4 Bv = rB[u], Cv = rC[u];
            int tn = t + u + PF;
            if (tn < SEQ) {
                rB[u]  = *(const float4*)(Bcol + (size_t)tn * CONVCH);
                rC[u]  = *(const float4*)(Ccol + (size_t)tn * CONVCH);
                rx[u]  = Xcol[(size_t)tn * CONVCH];
                rdt[u] = dtb[(size_t)tn * NHEADS + h];
                rdA[u] = dab[(size_t)tn * NHEADS + h];
            }
            float dtx = dt * x;
            s0 = s0 * dA + dtx * Bv.x; float acc = s0 * Cv.x;
            s1 = s1 * dA + dtx * Bv.y; acc += s1 * Cv.y;
            s2 = s2 * dA + dtx * Bv.z; acc += s2 * Cv.z;
            s3 = s3 * dA + dtx * Bv.w; acc += s3 * Cv.w;
            acc += __shfl_xor_sync(0xffffffffu, acc, 1);
            acc += __shfl_xor_sync(0xffffffffu, acc, 2);
            acc += __shfl_xor_sync(0xffffffffu, acc, 4);
            acc += __shfl_xor_sync(0xffffffffu, acc, 8);
            if (writer)
                yb[(size_t)(t + u) * DINNER + h * HD + p] = acc + Dh * x;
        }
    }
}

// ---------------- SwiGLU -> bf16 g ----------------
__global__ __launch_bounds__(256) void swiglu_kernel()
{
    int gid = blockIdx.x * 256 + threadIdx.x;
    if (gid >= SEQ * FFN) return;
    float g = g_buf[OFF_G + gid];
    float u = g_buf[OFF_U + gid];
    float v = siluf(g) * u;
    __nv_bfloat16 h, l; bf_split(v, h, l);
    g_bf[BF_G + gid] = h;
    g_bf[BF_G + N_G + gid] = l;
}

// ---------------- bf16-split HMMA GEMM: O[M,N] = A[M,K] @ W[N,K]^T (+res) ----------------
// 128x128 block tile, BK=32, cp.async double-buffered, ldmatrix fragments,
// mma.sync.m16n8k16.bf16 with 3-way hi/lo split. Row stride 80B (conflict-free).
#define RS 80                       // bytes per smem row (64 data + 16 pad)
#define BUFB (128 * RS)             // 10240 per buffer
#define STAGEB (4 * BUFB)           // Ah,Al,Bh,Bl
constexpr int GEMM_SMEM = 2 * STAGEB;  // 81920

__global__ __launch_bounds__(256) void gemm_bf(
    size_t a_hi, size_t a_n,
    size_t w_hi, size_t w_n,
    const float* __restrict__ Re, size_t roff, int has_res,
    float* __restrict__ Oe, size_t ooff,
    int M, int N, int K)
{
    extern __shared__ char smem[];
    const uint32_t sb = smem_u32(smem);
    const int tid  = threadIdx.x;
    const int lane = tid & 31;
    const int wid  = tid >> 5;
    const int wm   = (wid & 1) * 64;
    const int wn   = (wid >> 1) * 32;
    const int bm   = blockIdx.y * 128;
    const int bn   = blockIdx.x * 128;
    const int g    = lane >> 2;
    const int cc   = lane & 3;

    const __nv_bfloat16* Ah = g_bf + a_hi;
    const __nv_bfloat16* Al = Ah + a_n;
    const __nv_bfloat16* Wh = g_bf + w_hi;
    const __nv_bfloat16* Wl = Wh + w_n;

    // staging: thread -> (row, half): 32B of a 64B row per buffer
    const int srow = tid >> 1;
    const int shalf = tid & 1;
    const uint32_t sdst = (uint32_t)(srow * RS + shalf * 32);

    // ldmatrix per-lane addresses
    const int l15 = lane & 15;
    const int lhi = (lane >> 4) & 1;
    const uint32_t aoff = (uint32_t)((wm + l15) * RS + lhi * 16);
    const uint32_t boff = (uint32_t)(2 * BUFB + (wn + l15) * RS + lhi * 16);

    float acc[4][4][4];
    #pragma unroll
    for (int i = 0; i < 4; i++)
        #pragma unroll
        for (int j = 0; j < 4; j++)
            #pragma unroll
            for (int q = 0; q < 4; q++) acc[i][j][q] = 0.f;

    const int KT = K >> 5;

    // issue cp.async for chunk kc into stage st
    auto issue = [&](int kc, int st) {
        uint32_t d = sb + st * STAGEB + sdst;
        size_t ga = (size_t)(bm + srow) * K + (size_t)kc * 32 + shalf * 16;
        CP_ASYNC16(d,            Ah + ga,     16);
        CP_ASYNC16(d + 16,       Ah + ga + 8, 16);
        CP_ASYNC16(d + BUFB,     Al + ga,     16);
        CP_ASYNC16(d + BUFB + 16, Al + ga + 8, 16);
        int n = bn + srow;
        int ok = (n < N);
        int sz = ok ? 16 : 0;
        size_t gw = ok ? ((size_t)n * K + (size_t)kc * 32 + shalf * 16) : 0;
        CP_ASYNC16(d + 2 * BUFB,      Wh + gw,     sz);
        CP_ASYNC16(d + 2 * BUFB + 16, Wh + gw + 8, sz);
        CP_ASYNC16(d + 3 * BUFB,      Wl + gw,     sz);
        CP_ASYNC16(d + 3 * BUFB + 16, Wl + gw + 8, sz);
        CP_COMMIT();
    };

    issue(0, 0);
    for (int kc = 0; kc < KT; kc++) {
        const int st = kc & 1;
        if (kc + 1 < KT) { issue(kc + 1, st ^ 1); CP_WAIT1(); }
        else             { CP_WAIT0(); }
        __syncthreads();

        const uint32_t base = sb + st * STAGEB;
        #pragma unroll
        for (int s = 0; s < 2; s++) {
            uint32_t ah[4][4], al[4][4], bh[2][4], bl[2][4];
            #pragma unroll
            for (int i = 0; i < 4; i++) {
                uint32_t ad = base + aoff + i * (16 * RS) + s * 32;
                ldsm4(ah[i], ad);
                ldsm4(al[i], ad + BUFB);
            }
            #pragma unroll
            for (int jp = 0; jp < 2; jp++) {
                uint32_t bd = base + boff + jp * (16 * RS) + s * 32;
                ldsm4(bh[jp], bd);
                ldsm4(bl[jp], bd + BUFB);
            }
            #pragma unroll
            for (int i = 0; i < 4; i++) {
                #pragma unroll
                for (int j = 0; j < 4; j++) {
                    int jp = j >> 1, sel = j & 1;
                    uint32_t b0h = bh[jp][sel], b1h = bh[jp][sel + 2];
                    uint32_t b0l = bl[jp][sel], b1l = bl[jp][sel + 2];
                    mma16(acc[i][j], ah[i], b0h, b1h);   // hi*hi
                    mma16(acc[i][j], al[i], b0h, b1h);   // lo*hi
                    mma16(acc[i][j], ah[i], b0l, b1l);   // hi*lo
                }
            }
        }
        __syncthreads();
    }

    // ---- epilogue (same fragment->gmem mapping as proven R4 kernel) ----
    const float* R = has_res ? RP(Re, roff) : nullptr;
    float* O = WP(Oe, ooff);
    #pragma unroll
    for (int i = 0; i < 4; i++) {
        int row = bm + wm + i * 16 + g;
        #pragma unroll
        for (int j = 0; j < 4; j++) {
            int col = bn + wn + j * 8 + 2 * cc;
            if (col < N) {
                size_t o0 = (size_t)row * N + col;
                size_t o1 = (size_t)(row + 8) * N + col;
                float2 v0 = make_float2(acc[i][j][0], acc[i][j][1]);
                float2 v1 = make_float2(acc[i][j][2], acc[i][j][3]);
                if (has_res) {
                    float2 q0 = *(const float2*)(R + o0);
                    float2 q1 = *(const float2*)(R + o1);
                    v0.x += q0.x; v0.y += q0.y;
                    v1.x += q1.x; v1.y += q1.y;
                }
                *(float2*)(O + o0) = v0;
                *(float2*)(O + o1) = v1;
            }
        }
    }
}

// ---------------- launch ----------------
extern "C" void kernel_launch(void* const* d_in, const int* in_sizes, int n_in,
                              void* d_out, int out_size)
{
    const float* x          = (const float*)d_in[0];
    const float* norm1_w    = (const float*)d_in[1];
    const float* norm2_w    = (const float*)d_in[2];
    const float* in_proj_w  = (const float*)d_in[3];
    const float* conv_w     = (const float*)d_in[4];
    const float* conv_b     = (const float*)d_in[5];
    const float* dt_bias    = (const float*)d_in[6];
    const float* A_log      = (const float*)d_in[7];
    const float* Dv         = (const float*)d_in[8];
    const float* ssm_norm_w = (const float*)d_in[9];
    const float* out_proj_w = (const float*)d_in[10];
    const float* gate_w     = (const float*)d_in[11];
    const float* up_w       = (const float*)d_in[12];
    const float* down_w     = (const float*)d_in[13];
    float* out = (float*)d_out;

    cudaFuncSetAttribute(gemm_bf, cudaFuncAttributeMaxDynamicSharedMemorySize, GEMM_SMEM);

    // 0) weight fp32 -> bf16 hi/lo
    f2bf_kernel<<<256, 256>>>(in_proj_w,  0, BF_W_IN,   N_W_IN);
    f2bf_kernel<<<128, 256>>>(out_proj_w, 0, BF_W_OUT,  N_W_OUT);
    f2bf_kernel<<<160, 256>>>(gate_w,     0, BF_W_GATE, N_W_GATE);
    f2bf_kernel<<<160, 256>>>(up_w,       0, BF_W_UP,   N_W_UP);
    f2bf_kernel<<<160, 256>>>(down_w,     0, BF_W_DOWN, N_W_DOWN);

    // 1) xn = rmsnorm(x) (fp32 + bf16 split)
    rmsnorm_kernel<<<SEQ, 256>>>(x, 0, norm1_w, nullptr, OFF_XN, BF_XN, N_XN, DM, EPS1);

    // 2) zxbcdt = xn @ in_proj_w^T
    gemm_bf<<<dim3((DIP + 127) / 128, SEQ / 128), 256, GEMM_SMEM>>>(
        BF_XN, N_XN, BF_W_IN, N_W_IN, nullptr, 0, 0, nullptr, OFF_ZX, SEQ, DIP, DM);

    // 3) conv + silu
    conv_silu_kernel<<<(SEQ * CONVCH + 255) / 256, 256>>>(conv_w, conv_b);

    // 4) dt exact + dA
    dtprep_kernel<<<SEQ, 128>>>(in_proj_w, dt_bias, A_log);

    // 5) SSM scan
    scan_kernel<<<NHEADS * 4, 256>>>(Dv);

    // 6) gated rmsnorm -> bf16 y
    gated_norm_kernel<<<SEQ, 256>>>(ssm_norm_w);

    // 7) x1 = y @ out_proj_w^T + x
    gemm_bf<<<dim3(DM / 128, SEQ / 128), 256, GEMM_SMEM>>>(
        BF_Y, N_Y, BF_W_OUT, N_W_OUT, x, 0, 1, nullptr, OFF_X1, SEQ, DM, DINNER);

    // 8) h = rmsnorm(x1) -> bf16
    rmsnorm_kernel<<<SEQ, 256>>>(nullptr, OFF_X1, norm2_w, nullptr, OFF_H, BF_H, N_H, DM, EPS1);

    // 9) g = h @ gate_w^T ; u = h @ up_w^T
    gemm_bf<<<dim3(FFN / 128, SEQ / 128), 256, GEMM_SMEM>>>(
        BF_H, N_H, BF_W_GATE, N_W_GATE, nullptr, 0, 0, nullptr, OFF_G, SEQ, FFN, DM);
    gemm_bf<<<dim3(FFN / 128, SEQ / 128), 256, GEMM_SMEM>>>(
        BF_H, N_H, BF_W_UP, N_W_UP, nullptr, 0, 0, nullptr, OFF_U, SEQ, FFN, DM);

    // 10) g = silu(g)*u -> bf16
    swiglu_kernel<<<(SEQ * FFN + 255) / 256, 256>>>();

    // 11) out = g @ down_w^T + x1
    gemm_bf<<<dim3(DM / 128, SEQ / 128), 256, GEMM_SMEM>>>(
        BF_G, N_G, BF_W_DOWN, N_W_DOWN, nullptr, OFF_X1, 1, out, 0, SEQ, DM, FFN);
}